// round 12
// baseline (speedup 1.0000x reference)
#include <cuda_runtime.h>
#include <cuda_bf16.h>
#include <math.h>
#include <stdint.h>

#define D 2048
#define H 8192
#define NL 4
#define GRID 296
#define NW 8
#define WTOT (GRID * NW)   // 2368

// Scratch (device globals; no allocation allowed)
__device__ float g_x[D];
__device__ float g_rrk[3 * D];
__device__ float g_sx[D];
__device__ float g_kk[H];
__device__ float g_r[D];

__device__ __forceinline__ float warp_sum(float v) {
#pragma unroll
    for (int o = 16; o; o >>= 1) v += __shfl_xor_sync(0xffffffffu, v, o);
    return v;
}

__device__ __forceinline__ float d4(const float4 a, const float4 b) {
    return a.x * b.x + a.y * b.y + a.z * b.z + a.w * b.w;
}

// 256-thread block sum
__device__ __forceinline__ float block_sum(float v, float* sred) {
    v = warp_sum(v);
    int w = threadIdx.x >> 5, lane = threadIdx.x & 31;
    if (lane == 0) sred[w] = v;
    __syncthreads();
    float t = (threadIdx.x < NW) ? sred[threadIdx.x] : 0.f;
    if (w == 0) {
        t = warp_sum(t);
        if (lane == 0) sred[0] = t;
    }
    __syncthreads();
    float r = sred[0];
    __syncthreads();
    return r;
}

// ---- mbarrier + bulk-DMA helpers ----
__device__ __forceinline__ unsigned smem_u32(const void* p) {
    return (unsigned)__cvta_generic_to_shared(p);
}
__device__ __forceinline__ void mbar_init(unsigned mbar, unsigned count) {
    asm volatile("mbarrier.init.shared.b64 [%0], %1;" :: "r"(mbar), "r"(count) : "memory");
}
__device__ __forceinline__ void mbar_expect_tx(unsigned mbar, unsigned bytes) {
    asm volatile("mbarrier.arrive.expect_tx.shared.b64 _, [%0], %1;"
                 :: "r"(mbar), "r"(bytes) : "memory");
}
__device__ __forceinline__ void bulk_g2s(unsigned sdst, const void* gsrc,
                                         unsigned bytes, unsigned mbar) {
    asm volatile("cp.async.bulk.shared::cluster.global.mbarrier::complete_tx::bytes "
                 "[%0], [%1], %2, [%3];"
                 :: "r"(sdst), "l"(gsrc), "r"(bytes), "r"(mbar) : "memory");
}
__device__ __forceinline__ void mbar_wait(unsigned mbar, unsigned parity) {
    asm volatile(
        "{\n\t"
        ".reg .pred P1;\n\t"
        "WAIT_%=:\n\t"
        "mbarrier.try_wait.parity.acquire.cta.shared::cta.b64 P1, [%0], %1, 0x989680;\n\t"
        "@P1 bra DONE_%=;\n\t"
        "bra WAIT_%=;\n\t"
        "DONE_%=:\n\t"
        "}"
        :: "r"(mbar), "r"(parity) : "memory");
}

// 4KB tile dot: 256 f4, 8 per lane, 4 accumulators.
__device__ __forceinline__ float dot_tile4k(const float4* __restrict__ sbuf,
                                            const float4* __restrict__ svec, int lane) {
    float a0 = 0.f, a1 = 0.f, a2 = 0.f, a3 = 0.f;
#pragma unroll
    for (int u = 0; u < 8; u += 4) {
        a0 += d4(sbuf[lane + u * 32],       svec[lane + u * 32]);
        a1 += d4(sbuf[lane + (u + 1) * 32], svec[lane + (u + 1) * 32]);
        a2 += d4(sbuf[lane + (u + 2) * 32], svec[lane + (u + 2) * 32]);
        a3 += d4(sbuf[lane + (u + 3) * 32], svec[lane + (u + 3) * 32]);
    }
    return (a0 + a1) + (a2 + a3);
}

__global__ __launch_bounds__(256) void kcopy(const float* __restrict__ x) {
    int i = blockIdx.x * 256 + threadIdx.x;
    if (i < D) g_x[i] = x[i];
}

// ============ Stage B: LN1 + g_rrk = key@xn + keymul@state0 ============
// Warp owns pairs p = gw + k*WTOT; pair = key row (2 tiles, xn) + keymul row (2 tiles, sr).
// Depth-3 per-warp pipeline.
__global__ __launch_bounds__(256, 2) void kB(
    const float* __restrict__ state,
    const float* __restrict__ ln1w, const float* __restrict__ ln1b,
    const float* __restrict__ key, const float* __restrict__ keymul,
    float* __restrict__ out_state, int l)
{
    extern __shared__ __align__(16) float smem[];
    float4* bufs = (float4*)smem;            // 8 warps * 3 * 256 f4 = 96KB
    float* s_xn = smem + 24576;
    float* s_sr = s_xn + 2048;
    __shared__ float sred[NW + 1];
    __shared__ __align__(8) unsigned long long s_mbar[3 * NW];
    int tid = threadIdx.x, warp = tid >> 5, lane = tid & 31;
    int gw = blockIdx.x * NW + warp;
    const float* kbase = key    + (size_t)l * 3 * D * D;
    const float* mbase = keymul + (size_t)l * 3 * D * D;
    float4* wbuf = bufs + warp * 768;
    unsigned mb[3] = { smem_u32(&s_mbar[3 * warp]), smem_u32(&s_mbar[3 * warp + 1]),
                       smem_u32(&s_mbar[3 * warp + 2]) };

    if (tid < 3 * NW) mbar_init(smem_u32(&s_mbar[tid]), 1);
    __syncthreads();

    int npairs = 0;
    for (int p = gw; p < 3 * D; p += WTOT) npairs++;
    int ntiles = 4 * npairs;
    auto src = [&](int t) -> const float4* {
        int p = gw + (t >> 2) * WTOT;
        int sub = t & 3;
        const float* base = (sub < 2) ? kbase : mbase;
        return (const float4*)(base + (size_t)p * D) + (sub & 1) * 256;
    };
    if (lane == 0) {
#pragma unroll
        for (int q = 0; q < 3; q++) if (q < ntiles) {
            mbar_expect_tx(mb[q], 4096);
            bulk_g2s(smem_u32(wbuf + q * 256), src(q), 4096, mb[q]);
        }
    }

    // LN1 prologue (overlaps first DMAs)
    const float* srow = state + (size_t)(5 * l) * D;
    float ls = 0.f;
    for (int i = tid; i < D; i += 256) {
        float xv = g_x[i];
        s_xn[i] = xv; ls += xv;
        s_sr[i] = srow[i];
    }
    float m = block_sum(ls, sred) * (1.f / D);
    float lv = 0.f;
    for (int i = tid; i < D; i += 256) { float d0 = s_xn[i] - m; lv += d0 * d0; }
    float var = block_sum(lv, sred) * (1.f / D);
    float rs = rsqrtf(var + 1e-5f);
    const float* w = ln1w + (size_t)l * D;
    const float* b = ln1b + (size_t)l * D;
    for (int i = tid; i < D; i += 256)
        s_xn[i] = (s_xn[i] - m) * rs * w[i] + b[i];
    __syncthreads();
    if (blockIdx.x == 0) {
        float* xnrow = out_state + (size_t)(5 * l + 0) * D;
        for (int i = tid; i < D; i += 256) xnrow[i] = s_xn[i];
    }

    const float4* xn4 = (const float4*)s_xn;
    const float4* sr4 = (const float4*)s_sr;
    unsigned ph[3] = { 0, 0, 0 };
    int sl = 0;
    float acc = 0.f;
    for (int t = 0; t < ntiles; t++) {
        mbar_wait(mb[sl], ph[sl]); ph[sl] ^= 1;
        int sub = t & 3;
        const float4* V = ((sub < 2) ? xn4 : sr4) + (sub & 1) * 256;
        acc += dot_tile4k(wbuf + sl * 256, V, lane);
        __syncwarp();
        int tn = t + 3;
        if (lane == 0 && tn < ntiles) {
            mbar_expect_tx(mb[sl], 4096);
            bulk_g2s(smem_u32(wbuf + sl * 256), src(tn), 4096, mb[sl]);
        }
        if (sub == 3) {
            float a = warp_sum(acc);
            if (lane == 0) g_rrk[gw + (t >> 2) * WTOT] = a;
            acc = 0.f;
        }
        if (++sl == 3) sl = 0;
    }
}

// ============ Stage C: WKV epilogue + sx = x + outputv[l] @ rab ============
__global__ __launch_bounds__(256, 2) void kC(
    const float* __restrict__ state,
    const float* __restrict__ td, const float* __restrict__ tf,
    const float* __restrict__ ow,
    float* __restrict__ out_state, int l)
{
    extern __shared__ __align__(16) float smem[];
    float4* bufs = (float4*)smem;            // 96KB
    float* s_v = smem + 24576;               // 2048 f
    __shared__ __align__(8) unsigned long long s_mbar[3 * NW];
    int tid = threadIdx.x, warp = tid >> 5, lane = tid & 31;
    int gw = blockIdx.x * NW + warp;
    const float* obase = ow + (size_t)l * D * D;
    float4* wbuf = bufs + warp * 768;
    unsigned mb[3] = { smem_u32(&s_mbar[3 * warp]), smem_u32(&s_mbar[3 * warp + 1]),
                       smem_u32(&s_mbar[3 * warp + 2]) };

    if (tid < 3 * NW) mbar_init(smem_u32(&s_mbar[tid]), 1);
    __syncthreads();

    int nrows = 0;
    for (int r = gw; r < D; r += WTOT) nrows++;
    int ntiles = 2 * nrows;
    auto src = [&](int t) -> const float4* {
        int r = gw + (t >> 1) * WTOT;
        return (const float4*)(obase + (size_t)r * D) + (t & 1) * 256;
    };
    if (lane == 0) {
#pragma unroll
        for (int q = 0; q < 3; q++) if (q < ntiles) {
            mbar_expect_tx(mb[q], 4096);
            bulk_g2s(smem_u32(wbuf + q * 256), src(q), 4096, mb[q]);
        }
    }

    // WKV epilogue -> s_v (rab); block 0 writes state rows 1-3
    for (int i = tid; i < D; i += 256) {
        float k  = g_rrk[i];
        float v  = g_rrk[D + i];
        float rr = g_rrk[2 * D + i];
        float aa = state[(size_t)(5 * l + 1) * D + i];
        float bb = state[(size_t)(5 * l + 2) * D + i];
        float pp = state[(size_t)(5 * l + 3) * D + i];
        float tfi = tf[(size_t)l * D + i];
        float tdi = td[(size_t)l * D + i];
        float rsig = 1.f / (1.f + expf(-rr));
        float ww = tfi + k;
        float q = fmaxf(pp, ww);
        float e1 = expf(pp - q), e2 = expf(ww - q);
        float a_ = e1 * aa + e2 * v;
        float b_ = e1 * bb + e2;
        s_v[i] = rsig * (a_ / b_);
        if (blockIdx.x == 0) {
            float ww2 = pp + tdi;
            float q2 = fmaxf(ww2, k);
            float f1 = expf(ww2 - q2), f2 = expf(k - q2);
            out_state[(size_t)(5 * l + 1) * D + i] = f1 * aa + f2 * v;
            out_state[(size_t)(5 * l + 2) * D + i] = f1 * bb + f2;
            out_state[(size_t)(5 * l + 3) * D + i] = q2;
        }
    }
    __syncthreads();

    const float4* v4 = (const float4*)s_v;
    unsigned ph[3] = { 0, 0, 0 };
    int sl = 0;
    float acc = 0.f;
    for (int t = 0; t < ntiles; t++) {
        mbar_wait(mb[sl], ph[sl]); ph[sl] ^= 1;
        acc += dot_tile4k(wbuf + sl * 256, v4 + (t & 1) * 256, lane);
        __syncwarp();
        int tn = t + 3;
        if (lane == 0 && tn < ntiles) {
            mbar_expect_tx(mb[sl], 4096);
            bulk_g2s(smem_u32(wbuf + sl * 256), src(tn), 4096, mb[sl]);
        }
        if (t & 1) {
            float a = warp_sum(acc);
            int r = gw + (t >> 1) * WTOT;
            if (lane == 0) g_sx[r] = g_x[r] + a;
            acc = 0.f;
        }
        if (++sl == 3) sl = 0;
    }
}

// ============ Stage E: LN2 + kk = relu(kffn@dx)^2 ; r = sigmoid(rffn@xr) ============
__global__ __launch_bounds__(256, 2) void kE(
    const float* __restrict__ state,
    const float* __restrict__ ln2w, const float* __restrict__ ln2b,
    const float* __restrict__ tmk, const float* __restrict__ tmr,
    const float* __restrict__ kffn, const float* __restrict__ rffn,
    float* __restrict__ out_state, int l)
{
    extern __shared__ __align__(16) float smem[];
    float4* bufs = (float4*)smem;            // 96KB
    float* s_dx = smem + 24576;
    float* s_xr = s_dx + 2048;
    __shared__ float sred[NW + 1];
    __shared__ __align__(8) unsigned long long s_mbar[3 * NW];
    int tid = threadIdx.x, warp = tid >> 5, lane = tid & 31;
    int gw = blockIdx.x * NW + warp;
    const float* kbase = kffn + (size_t)l * H * D;
    const float* rbase = rffn + (size_t)l * D * D;
    float4* wbuf = bufs + warp * 768;
    unsigned mb[3] = { smem_u32(&s_mbar[3 * warp]), smem_u32(&s_mbar[3 * warp + 1]),
                       smem_u32(&s_mbar[3 * warp + 2]) };

    if (tid < 3 * NW) mbar_init(smem_u32(&s_mbar[tid]), 1);
    __syncthreads();

    const int NR = H + D;
    int nrows = 0;
    for (int r = gw; r < NR; r += WTOT) nrows++;
    int ntiles = 2 * nrows;
    auto src = [&](int t) -> const float4* {
        int r = gw + (t >> 1) * WTOT;
        const float* base = (r < H) ? kbase + (size_t)r * D : rbase + (size_t)(r - H) * D;
        return (const float4*)base + (t & 1) * 256;
    };
    if (lane == 0) {
#pragma unroll
        for (int q = 0; q < 3; q++) if (q < ntiles) {
            mbar_expect_tx(mb[q], 4096);
            bulk_g2s(smem_u32(wbuf + q * 256), src(q), 4096, mb[q]);
        }
    }

    // LN2 prologue (overlaps first DMAs)
    float ls = 0.f;
    for (int i = tid; i < D; i += 256) { float v = g_sx[i]; s_dx[i] = v; ls += v; }
    float m = block_sum(ls, sred) * (1.f / D);
    float lv = 0.f;
    for (int i = tid; i < D; i += 256) { float d0 = s_dx[i] - m; lv += d0 * d0; }
    float var = block_sum(lv, sred) * (1.f / D);
    float rs = rsqrtf(var + 1e-5f);
    const float* w  = ln2w + (size_t)l * D;
    const float* b  = ln2b + (size_t)l * D;
    const float* sf = state + (size_t)(5 * l + 4) * D;
    const float* tk = tmk + (size_t)l * D;
    const float* tr = tmr + (size_t)l * D;
    for (int i = tid; i < D; i += 256) {
        float x2n = (s_dx[i] - m) * rs * w[i] + b[i];
        float sfi = sf[i];
        if (blockIdx.x == 0) out_state[(size_t)(5 * l + 4) * D + i] = x2n;
        s_xr[i] = x2n + sfi * tr[i];
        s_dx[i] = x2n + sfi * tk[i];
    }
    __syncthreads();

    const float4* dx4 = (const float4*)s_dx;
    const float4* xr4 = (const float4*)s_xr;
    unsigned ph[3] = { 0, 0, 0 };
    int sl = 0;
    float acc = 0.f;
    for (int t = 0; t < ntiles; t++) {
        mbar_wait(mb[sl], ph[sl]); ph[sl] ^= 1;
        int r = gw + (t >> 1) * WTOT;
        const float4* V = ((r < H) ? dx4 : xr4) + (t & 1) * 256;
        acc += dot_tile4k(wbuf + sl * 256, V, lane);
        __syncwarp();
        int tn = t + 3;
        if (lane == 0 && tn < ntiles) {
            mbar_expect_tx(mb[sl], 4096);
            bulk_g2s(smem_u32(wbuf + sl * 256), src(tn), 4096, mb[sl]);
        }
        if (t & 1) {
            float a = warp_sum(acc);
            if (lane == 0) {
                if (r < H) { float rl = fmaxf(a, 0.f); g_kk[r] = rl * rl; }
                else g_r[r - H] = 1.f / (1.f + expf(-a));
            }
            acc = 0.f;
        }
        if (++sl == 3) sl = 0;
    }
}

// ============ Stage F: out = sx + r * (vffn[l] @ kk) ============
// Depth-2 (32KB vec); warp owns rows r = gw + k*WTOT (8 tiles each).
__global__ __launch_bounds__(256, 2) void kF(
    const float* __restrict__ vffn, float* __restrict__ xout, int l, int last)
{
    extern __shared__ __align__(16) float smem[];
    float4* bufs = (float4*)smem;            // 8 warps * 2 * 256 f4 = 64KB
    float* s_kk = smem + 16384;              // 8192 f
    __shared__ __align__(8) unsigned long long s_mbar[2 * NW];
    int tid = threadIdx.x, warp = tid >> 5, lane = tid & 31;
    int gw = blockIdx.x * NW + warp;
    const float* vbase = vffn + (size_t)l * D * H;
    float4* wbuf = bufs + warp * 512;
    unsigned mb[2] = { smem_u32(&s_mbar[2 * warp]), smem_u32(&s_mbar[2 * warp + 1]) };

    if (tid < 2 * NW) mbar_init(smem_u32(&s_mbar[tid]), 1);
    __syncthreads();

    int nrows = 0;
    for (int r = gw; r < D; r += WTOT) nrows++;
    int ntiles = 8 * nrows;
    auto src = [&](int t) -> const float4* {
        int r = gw + (t >> 3) * WTOT;
        return (const float4*)(vbase + (size_t)r * H) + (t & 7) * 256;
    };
    if (lane == 0) {
#pragma unroll
        for (int q = 0; q < 2; q++) if (q < ntiles) {
            mbar_expect_tx(mb[q], 4096);
            bulk_g2s(smem_u32(wbuf + q * 256), src(q), 4096, mb[q]);
        }
    }

    for (int i = tid; i < H; i += 256) s_kk[i] = g_kk[i];
    __syncthreads();

    const float4* kk4 = (const float4*)s_kk;
    unsigned ph0 = 0, ph1 = 0;
    float acc = 0.f;
    for (int t = 0; t < ntiles; t++) {
        int sl = t & 1;
        if (sl == 0) { mbar_wait(mb[0], ph0); ph0 ^= 1; }
        else         { mbar_wait(mb[1], ph1); ph1 ^= 1; }
        acc += dot_tile4k(wbuf + sl * 256, kk4 + (t & 7) * 256, lane);
        __syncwarp();
        int tn = t + 2;
        if (lane == 0 && tn < ntiles) {
            mbar_expect_tx(mb[sl], 4096);
            bulk_g2s(smem_u32(wbuf + sl * 256), src(tn), 4096, mb[sl]);
        }
        if ((t & 7) == 7) {
            float a = warp_sum(acc);
            int r = gw + (t >> 3) * WTOT;
            if (lane == 0) {
                float val = g_sx[r] + g_r[r] * a;
                if (last) xout[r] = val;
                else g_x[r] = val;
            }
            acc = 0.f;
        }
    }
}

extern "C" void kernel_launch(void* const* d_in, const int* in_sizes, int n_in,
                              void* d_out, int out_size)
{
    const float* x      = (const float*)d_in[0];
    const float* state  = (const float*)d_in[1];
    const float* ln1w   = (const float*)d_in[2];
    const float* ln1b   = (const float*)d_in[3];
    const float* ln2w   = (const float*)d_in[4];
    const float* ln2b   = (const float*)d_in[5];
    const float* td     = (const float*)d_in[6];
    const float* tf     = (const float*)d_in[7];
    const float* key    = (const float*)d_in[8];
    const float* keymul = (const float*)d_in[9];
    const float* ow     = (const float*)d_in[10];
    const float* tmk    = (const float*)d_in[11];
    const float* tmr    = (const float*)d_in[12];
    const float* kffn   = (const float*)d_in[13];
    const float* rffn   = (const float*)d_in[14];
    const float* vffn   = (const float*)d_in[15];

    float* out       = (float*)d_out;
    float* out_x     = out;       // [D]
    float* out_state = out + D;   // [L*5*D]

    const int SM_B = (24576 + 4096) * 4;   // 114688  (96KB bufs + 16KB vecs)
    const int SM_C = (24576 + 2048) * 4;   // 106496
    const int SM_E = (24576 + 4096) * 4;   // 114688
    const int SM_F = (16384 + 8192) * 4;   // 98304   (64KB bufs + 32KB vec)

    cudaFuncSetAttribute(kB, cudaFuncAttributeMaxDynamicSharedMemorySize, SM_B);
    cudaFuncSetAttribute(kC, cudaFuncAttributeMaxDynamicSharedMemorySize, SM_C);
    cudaFuncSetAttribute(kE, cudaFuncAttributeMaxDynamicSharedMemorySize, SM_E);
    cudaFuncSetAttribute(kF, cudaFuncAttributeMaxDynamicSharedMemorySize, SM_F);

    kcopy<<<(D + 255) / 256, 256>>>(x);
    for (int l = 0; l < NL; l++) {
        kB<<<GRID, 256, SM_B>>>(state, ln1w, ln1b, key, keymul, out_state, l);
        kC<<<GRID, 256, SM_C>>>(state, td, tf, ow, out_state, l);
        kE<<<GRID, 256, SM_E>>>(state, ln2w, ln2b, tmk, tmr, kffn, rffn, out_state, l);
        kF<<<GRID, 256, SM_F>>>(vffn, out_x, l, (l == NL - 1) ? 1 : 0);
    }
}

// round 13
// speedup vs baseline: 1.1457x; 1.1457x over previous
#include <cuda_runtime.h>
#include <cuda_bf16.h>
#include <math.h>
#include <stdint.h>

#define D 2048
#define H 8192
#define NL 4
#define GRID 148
#define NW 16
#define NDMA 8
#define WTOT (GRID * NW)   // 2368

// Scratch (device globals; no allocation allowed)
__device__ float g_x[D];
__device__ float g_rrk[3 * D];
__device__ float g_sx[D];
__device__ float g_kk[H];
__device__ float g_r[D];

__device__ __forceinline__ float warp_sum(float v) {
#pragma unroll
    for (int o = 16; o; o >>= 1) v += __shfl_xor_sync(0xffffffffu, v, o);
    return v;
}

__device__ __forceinline__ float d4(const float4 a, const float4 b) {
    return a.x * b.x + a.y * b.y + a.z * b.z + a.w * b.w;
}

// 512-thread block sum
__device__ __forceinline__ float block_sum(float v, float* sred) {
    v = warp_sum(v);
    int w = threadIdx.x >> 5, lane = threadIdx.x & 31;
    if (lane == 0) sred[w] = v;
    __syncthreads();
    float t = (threadIdx.x < NW) ? sred[threadIdx.x] : 0.f;
    if (w == 0) {
        t = warp_sum(t);
        if (lane == 0) sred[0] = t;
    }
    __syncthreads();
    float r = sred[0];
    __syncthreads();
    return r;
}

// ---- mbarrier + bulk-DMA helpers ----
__device__ __forceinline__ unsigned smem_u32(const void* p) {
    return (unsigned)__cvta_generic_to_shared(p);
}
__device__ __forceinline__ void mbar_init(unsigned mbar, unsigned count) {
    asm volatile("mbarrier.init.shared.b64 [%0], %1;" :: "r"(mbar), "r"(count) : "memory");
}
__device__ __forceinline__ void mbar_expect_tx(unsigned mbar, unsigned bytes) {
    asm volatile("mbarrier.arrive.expect_tx.shared.b64 _, [%0], %1;"
                 :: "r"(mbar), "r"(bytes) : "memory");
}
__device__ __forceinline__ void bulk_g2s(unsigned sdst, const void* gsrc,
                                         unsigned bytes, unsigned mbar) {
    asm volatile("cp.async.bulk.shared::cluster.global.mbarrier::complete_tx::bytes "
                 "[%0], [%1], %2, [%3];"
                 :: "r"(sdst), "l"(gsrc), "r"(bytes), "r"(mbar) : "memory");
}
__device__ __forceinline__ void mbar_wait(unsigned mbar, unsigned parity) {
    asm volatile(
        "{\n\t"
        ".reg .pred P1;\n\t"
        "WAIT_%=:\n\t"
        "mbarrier.try_wait.parity.acquire.cta.shared::cta.b64 P1, [%0], %1, 0x989680;\n\t"
        "@P1 bra DONE_%=;\n\t"
        "bra WAIT_%=;\n\t"
        "DONE_%=:\n\t"
        "}"
        :: "r"(mbar), "r"(parity) : "memory");
}

// 4KB smem tile dot: 256 f4, 8 per lane.
__device__ __forceinline__ float dot_tile4k(const float4* __restrict__ sbuf,
                                            const float4* __restrict__ svec, int lane) {
    float a0 = 0.f, a1 = 0.f, a2 = 0.f, a3 = 0.f;
#pragma unroll
    for (int u = 0; u < 8; u += 4) {
        a0 += d4(sbuf[lane + u * 32],       svec[lane + u * 32]);
        a1 += d4(sbuf[lane + (u + 1) * 32], svec[lane + (u + 1) * 32]);
        a2 += d4(sbuf[lane + (u + 2) * 32], svec[lane + (u + 2) * 32]);
        a3 += d4(sbuf[lane + (u + 3) * 32], svec[lane + (u + 3) * 32]);
    }
    return (a0 + a1) + (a2 + a3);
}

// Direct-LDG forced batch of 8 independent LDG.128 (256-f4 segment), then FMAs.
__device__ __forceinline__ float chunk8(const float4* __restrict__ r4,
                                        const float4* __restrict__ s4,
                                        int off, int lane) {
    float4 w[8];
#pragma unroll
    for (int u = 0; u < 8; u++) w[u] = __ldcs(r4 + off + lane + u * 32);
    float a0 = 0.f, a1 = 0.f;
#pragma unroll
    for (int u = 0; u < 8; u += 2) {
        a0 += d4(w[u],     s4[off + lane + u * 32]);
        a1 += d4(w[u + 1], s4[off + lane + (u + 1) * 32]);
    }
    return a0 + a1;
}

__global__ __launch_bounds__(256) void kcopy(const float* __restrict__ x) {
    int i = blockIdx.x * 256 + threadIdx.x;
    if (i < D) g_x[i] = x[i];
}

// ============ Stage B: LN1 + g_rrk = key@xn + keymul@state0 ============
__global__ __launch_bounds__(512, 1) void kB(
    const float* __restrict__ state,
    const float* __restrict__ ln1w, const float* __restrict__ ln1b,
    const float* __restrict__ key, const float* __restrict__ keymul,
    float* __restrict__ out_state, int l)
{
    extern __shared__ __align__(16) float smem[];
    float4* bufs = (float4*)smem;            // 8 DMA warps * 512 f4 = 64KB
    float* s_xn = smem + 16384;
    float* s_sr = s_xn + 2048;
    __shared__ float sred[NW + 1];
    __shared__ __align__(8) unsigned long long s_mbar[2 * NDMA];
    int tid = threadIdx.x, warp = tid >> 5, lane = tid & 31;
    int gw = blockIdx.x * NW + warp;
    const float* kbase = key    + (size_t)l * 3 * D * D;
    const float* mbase = keymul + (size_t)l * 3 * D * D;

    if (tid < 2 * NDMA) mbar_init(smem_u32(&s_mbar[tid]), 1);
    __syncthreads();

    int npairs = 0;
    for (int p = gw; p < 3 * D; p += WTOT) npairs++;
    int ntiles = 4 * npairs;
    auto src = [&](int t) -> const float4* {
        int p = gw + (t >> 2) * WTOT;
        int sub = t & 3;
        const float* base = (sub < 2) ? kbase : mbase;
        return (const float4*)(base + (size_t)p * D) + (sub & 1) * 256;
    };
    float4* wbuf = bufs + warp * 512;
    unsigned mb0 = smem_u32(&s_mbar[2 * warp]), mb1 = smem_u32(&s_mbar[2 * warp + 1]);
    if (warp < NDMA && lane == 0) {
        if (0 < ntiles) { mbar_expect_tx(mb0, 4096); bulk_g2s(smem_u32(wbuf), src(0), 4096, mb0); }
        if (1 < ntiles) { mbar_expect_tx(mb1, 4096); bulk_g2s(smem_u32(wbuf + 256), src(1), 4096, mb1); }
    }

    // LN1 prologue
    const float* srow = state + (size_t)(5 * l) * D;
    float ls = 0.f;
    for (int i = tid; i < D; i += 512) {
        float xv = g_x[i];
        s_xn[i] = xv; ls += xv;
        s_sr[i] = srow[i];
    }
    float m = block_sum(ls, sred) * (1.f / D);
    float lv = 0.f;
    for (int i = tid; i < D; i += 512) { float d0 = s_xn[i] - m; lv += d0 * d0; }
    float var = block_sum(lv, sred) * (1.f / D);
    float rs = rsqrtf(var + 1e-5f);
    const float* w = ln1w + (size_t)l * D;
    const float* b = ln1b + (size_t)l * D;
    for (int i = tid; i < D; i += 512)
        s_xn[i] = (s_xn[i] - m) * rs * w[i] + b[i];
    __syncthreads();
    if (blockIdx.x == 0) {
        float* xnrow = out_state + (size_t)(5 * l + 0) * D;
        for (int i = tid; i < D; i += 512) xnrow[i] = s_xn[i];
    }

    const float4* xn4 = (const float4*)s_xn;
    const float4* sr4 = (const float4*)s_sr;
    if (warp < NDMA) {
        unsigned ph0 = 0, ph1 = 0;
        float acc = 0.f;
        for (int t = 0; t < ntiles; t++) {
            int sl = t & 1;
            if (sl == 0) { mbar_wait(mb0, ph0); ph0 ^= 1; }
            else         { mbar_wait(mb1, ph1); ph1 ^= 1; }
            int sub = t & 3;
            const float4* V = ((sub < 2) ? xn4 : sr4) + (sub & 1) * 256;
            acc += dot_tile4k(wbuf + sl * 256, V, lane);
            __syncwarp();
            int tn = t + 2;
            if (lane == 0 && tn < ntiles) {
                unsigned mbx = sl ? mb1 : mb0;
                mbar_expect_tx(mbx, 4096);
                bulk_g2s(smem_u32(wbuf + sl * 256), src(tn), 4096, mbx);
            }
            if (sub == 3) {
                float a = warp_sum(acc);
                if (lane == 0) g_rrk[gw + (t >> 2) * WTOT] = a;
                acc = 0.f;
            }
        }
    } else {
        for (int p = gw; p < 3 * D; p += WTOT) {
            const float4* kr = (const float4*)(kbase + (size_t)p * D);
            const float4* mr = (const float4*)(mbase + (size_t)p * D);
            float acc = chunk8(kr, xn4, 0, lane) + chunk8(kr, xn4, 256, lane)
                      + chunk8(mr, sr4, 0, lane) + chunk8(mr, sr4, 256, lane);
            float a = warp_sum(acc);
            if (lane == 0) g_rrk[p] = a;
        }
    }
}

// ============ Stage C: WKV epilogue + sx = x + outputv[l] @ rab ============
__global__ __launch_bounds__(512, 1) void kC(
    const float* __restrict__ state,
    const float* __restrict__ td, const float* __restrict__ tf,
    const float* __restrict__ ow,
    float* __restrict__ out_state, int l)
{
    extern __shared__ __align__(16) float smem[];
    float4* bufs = (float4*)smem;            // 64KB
    float* s_v = smem + 16384;
    __shared__ __align__(8) unsigned long long s_mbar[2 * NDMA];
    int tid = threadIdx.x, warp = tid >> 5, lane = tid & 31;
    int gw = blockIdx.x * NW + warp;
    const float* obase = ow + (size_t)l * D * D;

    if (tid < 2 * NDMA) mbar_init(smem_u32(&s_mbar[tid]), 1);
    __syncthreads();

    int nrows = 0;
    for (int r = gw; r < D; r += WTOT) nrows++;
    int ntiles = 2 * nrows;
    auto src = [&](int t) -> const float4* {
        int r = gw + (t >> 1) * WTOT;
        return (const float4*)(obase + (size_t)r * D) + (t & 1) * 256;
    };
    float4* wbuf = bufs + warp * 512;
    unsigned mb0 = smem_u32(&s_mbar[2 * warp]), mb1 = smem_u32(&s_mbar[2 * warp + 1]);
    if (warp < NDMA && lane == 0) {
        if (0 < ntiles) { mbar_expect_tx(mb0, 4096); bulk_g2s(smem_u32(wbuf), src(0), 4096, mb0); }
        if (1 < ntiles) { mbar_expect_tx(mb1, 4096); bulk_g2s(smem_u32(wbuf + 256), src(1), 4096, mb1); }
    }

    // WKV epilogue -> s_v
    for (int i = tid; i < D; i += 512) {
        float k  = g_rrk[i];
        float v  = g_rrk[D + i];
        float rr = g_rrk[2 * D + i];
        float aa = state[(size_t)(5 * l + 1) * D + i];
        float bb = state[(size_t)(5 * l + 2) * D + i];
        float pp = state[(size_t)(5 * l + 3) * D + i];
        float tfi = tf[(size_t)l * D + i];
        float tdi = td[(size_t)l * D + i];
        float rsig = 1.f / (1.f + expf(-rr));
        float ww = tfi + k;
        float q = fmaxf(pp, ww);
        float e1 = expf(pp - q), e2 = expf(ww - q);
        float a_ = e1 * aa + e2 * v;
        float b_ = e1 * bb + e2;
        s_v[i] = rsig * (a_ / b_);
        if (blockIdx.x == 0) {
            float ww2 = pp + tdi;
            float q2 = fmaxf(ww2, k);
            float f1 = expf(ww2 - q2), f2 = expf(k - q2);
            out_state[(size_t)(5 * l + 1) * D + i] = f1 * aa + f2 * v;
            out_state[(size_t)(5 * l + 2) * D + i] = f1 * bb + f2;
            out_state[(size_t)(5 * l + 3) * D + i] = q2;
        }
    }
    __syncthreads();

    const float4* v4 = (const float4*)s_v;
    if (warp < NDMA) {
        unsigned ph0 = 0, ph1 = 0;
        float acc = 0.f;
        for (int t = 0; t < ntiles; t++) {
            int sl = t & 1;
            if (sl == 0) { mbar_wait(mb0, ph0); ph0 ^= 1; }
            else         { mbar_wait(mb1, ph1); ph1 ^= 1; }
            acc += dot_tile4k(wbuf + sl * 256, v4 + (t & 1) * 256, lane);
            __syncwarp();
            int tn = t + 2;
            if (lane == 0 && tn < ntiles) {
                unsigned mbx = sl ? mb1 : mb0;
                mbar_expect_tx(mbx, 4096);
                bulk_g2s(smem_u32(wbuf + sl * 256), src(tn), 4096, mbx);
            }
            if (t & 1) {
                float a = warp_sum(acc);
                int r = gw + (t >> 1) * WTOT;
                if (lane == 0) g_sx[r] = g_x[r] + a;
                acc = 0.f;
            }
        }
    } else {
        for (int r = gw; r < D; r += WTOT) {
            const float4* or4 = (const float4*)(obase + (size_t)r * D);
            float acc = chunk8(or4, v4, 0, lane) + chunk8(or4, v4, 256, lane);
            float a = warp_sum(acc);
            if (lane == 0) g_sx[r] = g_x[r] + a;
        }
    }
}

// ============ Stage E: LN2 + kk = relu(kffn@dx)^2 ; r = sigmoid(rffn@xr) ============
__global__ __launch_bounds__(512, 1) void kE(
    const float* __restrict__ state,
    const float* __restrict__ ln2w, const float* __restrict__ ln2b,
    const float* __restrict__ tmk, const float* __restrict__ tmr,
    const float* __restrict__ kffn, const float* __restrict__ rffn,
    float* __restrict__ out_state, int l)
{
    extern __shared__ __align__(16) float smem[];
    float4* bufs = (float4*)smem;            // 64KB
    float* s_dx = smem + 16384;
    float* s_xr = s_dx + 2048;
    __shared__ float sred[NW + 1];
    __shared__ __align__(8) unsigned long long s_mbar[2 * NDMA];
    int tid = threadIdx.x, warp = tid >> 5, lane = tid & 31;
    int gw = blockIdx.x * NW + warp;
    const float* kbase = kffn + (size_t)l * H * D;
    const float* rbase = rffn + (size_t)l * D * D;

    if (tid < 2 * NDMA) mbar_init(smem_u32(&s_mbar[tid]), 1);
    __syncthreads();

    const int NR = H + D;
    int nrows = 0;
    for (int r = gw; r < NR; r += WTOT) nrows++;
    int ntiles = 2 * nrows;
    auto src = [&](int t) -> const float4* {
        int r = gw + (t >> 1) * WTOT;
        const float* base = (r < H) ? kbase + (size_t)r * D : rbase + (size_t)(r - H) * D;
        return (const float4*)base + (t & 1) * 256;
    };
    float4* wbuf = bufs + warp * 512;
    unsigned mb0 = smem_u32(&s_mbar[2 * warp]), mb1 = smem_u32(&s_mbar[2 * warp + 1]);
    if (warp < NDMA && lane == 0) {
        if (0 < ntiles) { mbar_expect_tx(mb0, 4096); bulk_g2s(smem_u32(wbuf), src(0), 4096, mb0); }
        if (1 < ntiles) { mbar_expect_tx(mb1, 4096); bulk_g2s(smem_u32(wbuf + 256), src(1), 4096, mb1); }
    }

    // LN2 prologue
    float ls = 0.f;
    for (int i = tid; i < D; i += 512) { float v = g_sx[i]; s_dx[i] = v; ls += v; }
    float m = block_sum(ls, sred) * (1.f / D);
    float lv = 0.f;
    for (int i = tid; i < D; i += 512) { float d0 = s_dx[i] - m; lv += d0 * d0; }
    float var = block_sum(lv, sred) * (1.f / D);
    float rs = rsqrtf(var + 1e-5f);
    const float* w  = ln2w + (size_t)l * D;
    const float* b  = ln2b + (size_t)l * D;
    const float* sf = state + (size_t)(5 * l + 4) * D;
    const float* tk = tmk + (size_t)l * D;
    const float* tr = tmr + (size_t)l * D;
    for (int i = tid; i < D; i += 512) {
        float x2n = (s_dx[i] - m) * rs * w[i] + b[i];
        float sfi = sf[i];
        if (blockIdx.x == 0) out_state[(size_t)(5 * l + 4) * D + i] = x2n;
        s_xr[i] = x2n + sfi * tr[i];
        s_dx[i] = x2n + sfi * tk[i];
    }
    __syncthreads();

    const float4* dx4 = (const float4*)s_dx;
    const float4* xr4 = (const float4*)s_xr;
    if (warp < NDMA) {
        unsigned ph0 = 0, ph1 = 0;
        float acc = 0.f;
        for (int t = 0; t < ntiles; t++) {
            int sl = t & 1;
            if (sl == 0) { mbar_wait(mb0, ph0); ph0 ^= 1; }
            else         { mbar_wait(mb1, ph1); ph1 ^= 1; }
            int r = gw + (t >> 1) * WTOT;
            const float4* V = ((r < H) ? dx4 : xr4) + (t & 1) * 256;
            acc += dot_tile4k(wbuf + sl * 256, V, lane);
            __syncwarp();
            int tn = t + 2;
            if (lane == 0 && tn < ntiles) {
                unsigned mbx = sl ? mb1 : mb0;
                mbar_expect_tx(mbx, 4096);
                bulk_g2s(smem_u32(wbuf + sl * 256), src(tn), 4096, mbx);
            }
            if (t & 1) {
                float a = warp_sum(acc);
                if (lane == 0) {
                    if (r < H) { float rl = fmaxf(a, 0.f); g_kk[r] = rl * rl; }
                    else g_r[r - H] = 1.f / (1.f + expf(-a));
                }
                acc = 0.f;
            }
        }
    } else {
        for (int r = gw; r < NR; r += WTOT) {
            const float4* row = (r < H) ? (const float4*)(kbase + (size_t)r * D)
                                        : (const float4*)(rbase + (size_t)(r - H) * D);
            const float4* V = (r < H) ? dx4 : xr4;
            float acc = chunk8(row, V, 0, lane) + chunk8(row, V, 256, lane);
            float a = warp_sum(acc);
            if (lane == 0) {
                if (r < H) { float rl = fmaxf(a, 0.f); g_kk[r] = rl * rl; }
                else g_r[r - H] = 1.f / (1.f + expf(-a));
            }
        }
    }
}

// ============ Stage F: out = sx + r * (vffn[l] @ kk) ============
__global__ __launch_bounds__(512, 1) void kF(
    const float* __restrict__ vffn, float* __restrict__ xout, int l, int last)
{
    extern __shared__ __align__(16) float smem[];
    float4* bufs = (float4*)smem;            // 64KB
    float* s_kk = smem + 16384;              // 8192 f
    __shared__ __align__(8) unsigned long long s_mbar[2 * NDMA];
    int tid = threadIdx.x, warp = tid >> 5, lane = tid & 31;
    int gw = blockIdx.x * NW + warp;
    const float* vbase = vffn + (size_t)l * D * H;

    if (tid < 2 * NDMA) mbar_init(smem_u32(&s_mbar[tid]), 1);
    __syncthreads();

    int nrows = 0;
    for (int r = gw; r < D; r += WTOT) nrows++;
    int ntiles = 8 * nrows;
    auto src = [&](int t) -> const float4* {
        int r = gw + (t >> 3) * WTOT;
        return (const float4*)(vbase + (size_t)r * H) + (t & 7) * 256;
    };
    float4* wbuf = bufs + warp * 512;
    unsigned mb0 = smem_u32(&s_mbar[2 * warp]), mb1 = smem_u32(&s_mbar[2 * warp + 1]);
    if (warp < NDMA && lane == 0) {
        if (0 < ntiles) { mbar_expect_tx(mb0, 4096); bulk_g2s(smem_u32(wbuf), src(0), 4096, mb0); }
        if (1 < ntiles) { mbar_expect_tx(mb1, 4096); bulk_g2s(smem_u32(wbuf + 256), src(1), 4096, mb1); }
    }

    for (int i = tid; i < H; i += 512) s_kk[i] = g_kk[i];
    __syncthreads();

    const float4* kk4 = (const float4*)s_kk;
    if (warp < NDMA) {
        unsigned ph0 = 0, ph1 = 0;
        float acc = 0.f;
        for (int t = 0; t < ntiles; t++) {
            int sl = t & 1;
            if (sl == 0) { mbar_wait(mb0, ph0); ph0 ^= 1; }
            else         { mbar_wait(mb1, ph1); ph1 ^= 1; }
            acc += dot_tile4k(wbuf + sl * 256, kk4 + (t & 7) * 256, lane);
            __syncwarp();
            int tn = t + 2;
            if (lane == 0 && tn < ntiles) {
                unsigned mbx = sl ? mb1 : mb0;
                mbar_expect_tx(mbx, 4096);
                bulk_g2s(smem_u32(wbuf + sl * 256), src(tn), 4096, mbx);
            }
            if ((t & 7) == 7) {
                float a = warp_sum(acc);
                int r = gw + (t >> 3) * WTOT;
                if (lane == 0) {
                    float val = g_sx[r] + g_r[r] * a;
                    if (last) xout[r] = val;
                    else g_x[r] = val;
                }
                acc = 0.f;
            }
        }
    } else {
        for (int r = gw; r < D; r += WTOT) {
            const float4* row = (const float4*)(vbase + (size_t)r * H);
            float acc = 0.f;
#pragma unroll
            for (int c = 0; c < 8; c++)
                acc += chunk8(row, kk4, c * 256, lane);
            float a = warp_sum(acc);
            if (lane == 0) {
                float val = g_sx[r] + g_r[r] * a;
                if (last) xout[r] = val;
                else g_x[r] = val;
            }
        }
    }
}

extern "C" void kernel_launch(void* const* d_in, const int* in_sizes, int n_in,
                              void* d_out, int out_size)
{
    const float* x      = (const float*)d_in[0];
    const float* state  = (const float*)d_in[1];
    const float* ln1w   = (const float*)d_in[2];
    const float* ln1b   = (const float*)d_in[3];
    const float* ln2w   = (const float*)d_in[4];
    const float* ln2b   = (const float*)d_in[5];
    const float* td     = (const float*)d_in[6];
    const float* tf     = (const float*)d_in[7];
    const float* key    = (const float*)d_in[8];
    const float* keymul = (const float*)d_in[9];
    const float* ow     = (const float*)d_in[10];
    const float* tmk    = (const float*)d_in[11];
    const float* tmr    = (const float*)d_in[12];
    const float* kffn   = (const float*)d_in[13];
    const float* rffn   = (const float*)d_in[14];
    const float* vffn   = (const float*)d_in[15];

    float* out       = (float*)d_out;
    float* out_x     = out;       // [D]
    float* out_state = out + D;   // [L*5*D]

    const int SM_B = (16384 + 4096) * 4;   // 81920 (64KB bufs + 16KB vecs)
    const int SM_C = (16384 + 2048) * 4;   // 73728
    const int SM_E = (16384 + 4096) * 4;   // 81920
    const int SM_F = (16384 + 8192) * 4;   // 98304

    cudaFuncSetAttribute(kB, cudaFuncAttributeMaxDynamicSharedMemorySize, SM_B);
    cudaFuncSetAttribute(kC, cudaFuncAttributeMaxDynamicSharedMemorySize, SM_C);
    cudaFuncSetAttribute(kE, cudaFuncAttributeMaxDynamicSharedMemorySize, SM_E);
    cudaFuncSetAttribute(kF, cudaFuncAttributeMaxDynamicSharedMemorySize, SM_F);

    kcopy<<<(D + 255) / 256, 256>>>(x);
    for (int l = 0; l < NL; l++) {
        kB<<<GRID, 512, SM_B>>>(state, ln1w, ln1b, key, keymul, out_state, l);
        kC<<<GRID, 512, SM_C>>>(state, td, tf, ow, out_state, l);
        kE<<<GRID, 512, SM_E>>>(state, ln2w, ln2b, tmk, tmr, kffn, rffn, out_state, l);
        kF<<<GRID, 512, SM_F>>>(vffn, out_x, l, (l == NL - 1) ? 1 : 0);
    }
}